// round 7
// baseline (speedup 1.0000x reference)
#include <cuda_runtime.h>
#include <cuda_bf16.h>

#define N_NODES 50000
#define N_EDGES 800000
#define HID 64
#define IN_DIM 4
#define BN_EPS 1e-5f

#define SCAN_BLK 256
#define NBLK ((N_NODES + SCAN_BLK - 1) / SCAN_BLK)   // 196
static_assert(NBLK <= 256, "NBLK must fit one scan block");

// ---------------- scratch (static device globals; no allocation) ----------------
// Symbols passed as kernel args from host MUST be resolved with
// cudaGetSymbolAddress (bare symbol = host shadow; ATS silently reads host BSS).
__device__ __align__(16) int   g_deg[N_NODES];
__device__ __align__(16) float g_dinv[N_NODES];
__device__ __align__(16) int   g_rowptr[N_NODES + 1];
__device__ __align__(16) int   g_cursor[N_NODES];
__device__ __align__(16) int2  g_srcw[N_EDGES];          // (src, w-bits)
__device__ __align__(16) float g_h[N_NODES * HID];       // fp32 residual stream
__device__ __align__(16) __nv_bfloat162 g_hwb[N_NODES * HID / 2];  // bf16 message matrix
__device__ __align__(16) int   g_blocksum[NBLK];
__device__ __align__(16) int   g_blockoff[NBLK];

// ---------------- graph preprocessing ----------------
__global__ void zero_deg_kernel() {
    int i = blockIdx.x * blockDim.x + threadIdx.x;
    if (i < N_NODES) g_deg[i] = 0;
}

__global__ void count_deg_kernel(const int* __restrict__ edge_index) {
    int e = blockIdx.x * blockDim.x + threadIdx.x;
    if (e < N_EDGES) {
        int dst = edge_index[N_EDGES + e];   // row 1 of [2, E]
        atomicAdd(&g_deg[dst], 1);
    }
}

// stage 1: per-block tree reduction of degrees  (+ fused dinv computation)
__global__ void scan_reduce_kernel() {
    __shared__ int sdata[SCAN_BLK];
    int b = blockIdx.x, t = threadIdx.x;
    int i = b * SCAN_BLK + t;
    int d = (i < N_NODES) ? g_deg[i] : 0;
    if (i < N_NODES) g_dinv[i] = rsqrtf((float)(d + 1));  // +1 self loop
    sdata[t] = d;
    __syncthreads();
    #pragma unroll
    for (int s = SCAN_BLK / 2; s > 0; s >>= 1) {
        if (t < s) sdata[t] += sdata[t + s];
        __syncthreads();
    }
    if (t == 0) g_blocksum[b] = sdata[0];
}

// stage 2: one block scans the block sums (double-buffered)
__global__ void scan_offsets_kernel() {
    __shared__ int buf[2][256];
    int t = threadIdx.x;
    buf[0][t] = (t < NBLK) ? g_blocksum[t] : 0;
    int cur = 0;
    __syncthreads();
    #pragma unroll
    for (int off = 1; off < 256; off <<= 1) {
        int x = buf[cur][t];
        if (t >= off) x += buf[cur][t - off];
        buf[1 - cur][t] = x;
        cur = 1 - cur;
        __syncthreads();
    }
    if (t < NBLK) g_blockoff[t] = (t > 0) ? buf[cur][t - 1] : 0;
    if (t == NBLK - 1) g_rowptr[N_NODES] = buf[cur][t];
}

// stage 3: per-block scan of degrees + write rowptr/cursor
__global__ void scan_write_kernel() {
    __shared__ int buf[2][SCAN_BLK];
    int b = blockIdx.x, t = threadIdx.x;
    int i = b * SCAN_BLK + t;
    int v = (i < N_NODES) ? g_deg[i] : 0;
    buf[0][t] = v;
    int cur = 0;
    __syncthreads();
    #pragma unroll
    for (int off = 1; off < SCAN_BLK; off <<= 1) {
        int x = buf[cur][t];
        if (t >= off) x += buf[cur][t - off];
        buf[1 - cur][t] = x;
        cur = 1 - cur;
        __syncthreads();
    }
    int incl = buf[cur][t];
    int excl = incl - v + g_blockoff[b];
    if (i < N_NODES) {
        g_rowptr[i] = excl;
        g_cursor[i] = excl;
    }
}

__global__ void fill_kernel(const int* __restrict__ edge_index) {
    int e = blockIdx.x * blockDim.x + threadIdx.x;
    if (e < N_EDGES) {
        int src = edge_index[e];
        int dst = edge_index[N_EDGES + e];
        int pos = atomicAdd(&g_cursor[dst], 1);
        float w = g_dinv[src] * g_dinv[dst];
        g_srcw[pos] = make_int2(src, __float_as_int(w));
    }
}

// ---------------- input projection: h = x @ W_in + b_in ----------------
__global__ void in_proj_kernel(const float* __restrict__ x,
                               const float* __restrict__ W_in,
                               const float* __restrict__ b_in) {
    __shared__ float xs[64 * IN_DIM];
    __shared__ float Ws[IN_DIM * HID];
    __shared__ float bs[HID];
    int tid = threadIdx.x;
    int n0 = blockIdx.x * 64;

    if (tid < IN_DIM * HID) Ws[tid] = W_in[tid];
    if (tid < HID) bs[tid] = b_in[tid];
    {
        int node = n0 + (tid >> 2);
        xs[tid] = (node < N_NODES) ? x[n0 * IN_DIM + tid] : 0.f;
    }
    __syncthreads();

    int j = tid & 63;
    int ng = tid >> 6;
    float bj = bs[j];
    float w0 = Ws[0 * HID + j], w1 = Ws[1 * HID + j], w2 = Ws[2 * HID + j], w3 = Ws[3 * HID + j];
    #pragma unroll 4
    for (int nn = 0; nn < 16; nn++) {
        int nloc = ng * 16 + nn;
        int node = n0 + nloc;
        if (node < N_NODES) {
            const float* xr = &xs[nloc * IN_DIM];
            g_h[node * HID + j] = bj + xr[0] * w0 + xr[1] * w1 + xr[2] * w2 + xr[3] * w3;
        }
    }
}

// ---------------- 64x64 GEMM -> bf16 output: hwb = A @ W ----------------
// A, C are REAL device pointers (cudaGetSymbolAddress).
__global__ void gemm64_bf16_kernel(const float* __restrict__ A,
                                   const float* __restrict__ W,
                                   __nv_bfloat162* __restrict__ C) {
    __shared__ float hT[64 * 68];
    __shared__ float Ws[64 * 64];
    int tid = threadIdx.x;
    int n0 = blockIdx.x * 64;

    {
        const float4* W4 = (const float4*)W;
        float4* Ws4 = (float4*)Ws;
        #pragma unroll
        for (int i = tid; i < 1024; i += 256) Ws4[i] = W4[i];
    }
    {
        int nn = tid & 63;
        int kq4 = tid >> 6;
        int node = n0 + nn;
        const float4* A4 = (const float4*)A;
        #pragma unroll
        for (int q = 0; q < 4; q++) {
            int kq = kq4 * 4 + q;
            float4 hv = (node < N_NODES) ? A4[node * 16 + kq]
                                         : make_float4(0.f, 0.f, 0.f, 0.f);
            hT[(kq * 4 + 0) * 68 + nn] = hv.x;
            hT[(kq * 4 + 1) * 68 + nn] = hv.y;
            hT[(kq * 4 + 2) * 68 + nn] = hv.z;
            hT[(kq * 4 + 3) * 68 + nn] = hv.w;
        }
    }
    __syncthreads();

    int nq = tid & 15;
    int jq = tid >> 4;
    const float4* Ws4 = (const float4*)Ws;

    float4 acc0 = make_float4(0.f, 0.f, 0.f, 0.f);
    float4 acc1 = acc0, acc2 = acc0, acc3 = acc0;
    #pragma unroll
    for (int k = 0; k < 64; k++) {
        float4 wv = Ws4[k * 16 + jq];
        float4 hv = *(const float4*)&hT[k * 68 + nq * 4];
        acc0.x += hv.x * wv.x; acc0.y += hv.x * wv.y; acc0.z += hv.x * wv.z; acc0.w += hv.x * wv.w;
        acc1.x += hv.y * wv.x; acc1.y += hv.y * wv.y; acc1.z += hv.y * wv.z; acc1.w += hv.y * wv.w;
        acc2.x += hv.z * wv.x; acc2.y += hv.z * wv.y; acc2.z += hv.z * wv.z; acc2.w += hv.z * wv.w;
        acc3.x += hv.w * wv.x; acc3.y += hv.w * wv.y; acc3.z += hv.w * wv.z; acc3.w += hv.w * wv.w;
    }

    uint2* C2 = (uint2*)C;
    float4 accs[4] = {acc0, acc1, acc2, acc3};
    #pragma unroll
    for (int ni = 0; ni < 4; ni++) {
        int node = n0 + nq * 4 + ni;
        if (node < N_NODES) {
            float4 r = accs[ni];
            __nv_bfloat162 lo = __floats2bfloat162_rn(r.x, r.y);
            __nv_bfloat162 hi = __floats2bfloat162_rn(r.z, r.w);
            uint2 pk;
            pk.x = *(unsigned int*)&lo;
            pk.y = *(unsigned int*)&hi;
            C2[node * 16 + jq] = pk;   // row = 64 bf16 = 16 uint2
        }
    }
}

// ---------------- aggregate + BN + ReLU + residual (warp per node) ----------------
__global__ void agg_kernel(const float* __restrict__ conv_b,
                           const float* __restrict__ bn_gamma,
                           const float* __restrict__ bn_beta,
                           const float* __restrict__ bn_mean,
                           const float* __restrict__ bn_var) {
    int warp = (blockIdx.x * blockDim.x + threadIdx.x) >> 5;
    int lane = threadIdx.x & 31;
    if (warp >= N_NODES) return;
    int v = warp;

    float2* h2 = (float2*)g_h;

    float dv = g_dinv[v];
    float wself = dv * dv;
    float2 sv = __bfloat1622float2(g_hwb[v * 32 + lane]);
    float accx = sv.x * wself;
    float accy = sv.y * wself;

    int beg = g_rowptr[v];
    int end = g_rowptr[v + 1];
    for (int e = beg; e < end; e += 32) {
        int idx = e + lane;
        int2 p = make_int2(0, 0);
        if (idx < end) p = g_srcw[idx];
        int cnt = min(32, end - e);
        for (int j = 0; j < cnt; j++) {
            int s = __shfl_sync(0xffffffffu, p.x, j);
            float w = __int_as_float(__shfl_sync(0xffffffffu, p.y, j));
            float2 hv = __bfloat1622float2(g_hwb[s * 32 + lane]);
            accx += hv.x * w;
            accy += hv.y * w;
        }
    }

    float2 cb = ((const float2*)conv_b)[lane];
    float2 gm = ((const float2*)bn_gamma)[lane];
    float2 bt = ((const float2*)bn_beta)[lane];
    float2 mn = ((const float2*)bn_mean)[lane];
    float2 vr = ((const float2*)bn_var)[lane];
    float s0 = gm.x * rsqrtf(vr.x + BN_EPS);
    float s1 = gm.y * rsqrtf(vr.y + BN_EPS);
    float o0 = (accx + cb.x - mn.x) * s0 + bt.x;
    float o1 = (accy + cb.y - mn.y) * s1 + bt.y;
    o0 = fmaxf(o0, 0.f);
    o1 = fmaxf(o1, 0.f);
    float2 res = h2[v * 32 + lane];
    h2[v * 32 + lane] = make_float2(o0 + res.x, o1 + res.y);
}

// ---------------- fused output MLP: out = x + relu(h@W1+b1)@W2 + b2 ----------------
__global__ void out_fused_kernel(const float* __restrict__ A,   // g_h (device ptr)
                                 const float* __restrict__ W1,
                                 const float* __restrict__ b1,
                                 const float* __restrict__ W2,
                                 const float* __restrict__ b2,
                                 const float* __restrict__ x,
                                 float* __restrict__ out) {
    __shared__ float hT[64 * 68];
    __shared__ float Ws[64 * 64];
    __shared__ float ts[64 * 68];      // t tile, [node][64]
    __shared__ float W2s[HID * IN_DIM];
    __shared__ float b2s[IN_DIM];
    int tid = threadIdx.x;
    int n0 = blockIdx.x * 64;

    {
        const float4* W4 = (const float4*)W1;
        float4* Ws4 = (float4*)Ws;
        #pragma unroll
        for (int i = tid; i < 1024; i += 256) Ws4[i] = W4[i];
    }
    if (tid < HID * IN_DIM) W2s[tid] = W2[tid];
    if (tid < IN_DIM) b2s[tid] = b2[tid];
    {
        int nn = tid & 63;
        int kq4 = tid >> 6;
        int node = n0 + nn;
        const float4* A4 = (const float4*)A;
        #pragma unroll
        for (int q = 0; q < 4; q++) {
            int kq = kq4 * 4 + q;
            float4 hv = (node < N_NODES) ? A4[node * 16 + kq]
                                         : make_float4(0.f, 0.f, 0.f, 0.f);
            hT[(kq * 4 + 0) * 68 + nn] = hv.x;
            hT[(kq * 4 + 1) * 68 + nn] = hv.y;
            hT[(kq * 4 + 2) * 68 + nn] = hv.z;
            hT[(kq * 4 + 3) * 68 + nn] = hv.w;
        }
    }
    __syncthreads();

    int nq = tid & 15;
    int jq = tid >> 4;
    const float4* Ws4 = (const float4*)Ws;

    float4 acc0 = make_float4(0.f, 0.f, 0.f, 0.f);
    float4 acc1 = acc0, acc2 = acc0, acc3 = acc0;
    #pragma unroll
    for (int k = 0; k < 64; k++) {
        float4 wv = Ws4[k * 16 + jq];
        float4 hv = *(const float4*)&hT[k * 68 + nq * 4];
        acc0.x += hv.x * wv.x; acc0.y += hv.x * wv.y; acc0.z += hv.x * wv.z; acc0.w += hv.x * wv.w;
        acc1.x += hv.y * wv.x; acc1.y += hv.y * wv.y; acc1.z += hv.y * wv.z; acc1.w += hv.y * wv.w;
        acc2.x += hv.z * wv.x; acc2.y += hv.z * wv.y; acc2.z += hv.z * wv.z; acc2.w += hv.z * wv.w;
        acc3.x += hv.w * wv.x; acc3.y += hv.w * wv.y; acc3.z += hv.w * wv.z; acc3.w += hv.w * wv.w;
    }

    float4 bv = ((const float4*)b1)[jq];
    float4 accs[4] = {acc0, acc1, acc2, acc3};
    #pragma unroll
    for (int ni = 0; ni < 4; ni++) {
        int nloc = nq * 4 + ni;
        float4 r = accs[ni];
        r.x = fmaxf(r.x + bv.x, 0.f);
        r.y = fmaxf(r.y + bv.y, 0.f);
        r.z = fmaxf(r.z + bv.z, 0.f);
        r.w = fmaxf(r.w + bv.w, 0.f);
        *(float4*)&ts[nloc * 68 + jq * 4] = r;
    }
    __syncthreads();

    // tail: out[node][m] = x[node][m] + b2[m] + sum_l ts[node][l] * W2[l][m]
    int nloc = tid >> 2;
    int m = tid & 3;
    int node = n0 + nloc;
    float acc = 0.f;
    #pragma unroll
    for (int l = 0; l < 64; l++) {
        acc += ts[nloc * 68 + l] * W2s[l * IN_DIM + m];
    }
    if (node < N_NODES) {
        out[node * IN_DIM + m] = x[node * IN_DIM + m] + b2s[m] + acc;
    }
}

// ---------------- launch ----------------
extern "C" void kernel_launch(void* const* d_in, const int* in_sizes, int n_in,
                              void* d_out, int out_size) {
    const float* x          = (const float*)d_in[0];
    const int*   edge_index = (const int*)d_in[1];
    const float* W_in       = (const float*)d_in[2];
    const float* b_in       = (const float*)d_in[3];
    const float* conv_w     = (const float*)d_in[4];   // [3,64,64]
    const float* conv_b     = (const float*)d_in[5];   // [3,64]
    const float* bn_gamma   = (const float*)d_in[6];
    const float* bn_beta    = (const float*)d_in[7];
    const float* bn_mean    = (const float*)d_in[8];
    const float* bn_var     = (const float*)d_in[9];
    const float* W1         = (const float*)d_in[10];
    const float* b1         = (const float*)d_in[11];
    const float* W2         = (const float*)d_in[12];
    const float* b2         = (const float*)d_in[13];
    float* out = (float*)d_out;

    void* p_h = nullptr;
    void* p_hwb = nullptr;
    cudaGetSymbolAddress(&p_h, g_h);
    cudaGetSymbolAddress(&p_hwb, g_hwb);
    float* d_h = (float*)p_h;
    __nv_bfloat162* d_hwb = (__nv_bfloat162*)p_hwb;

    const int TPB = 256;
    const int gridN = (N_NODES + TPB - 1) / TPB;
    const int gridE = (N_EDGES + TPB - 1) / TPB;
    const int gridT = (N_NODES + 63) / 64;
    const int gridW = (N_NODES * 32 + TPB - 1) / TPB;   // warp per node

    // build graph structure
    zero_deg_kernel<<<gridN, TPB>>>();
    count_deg_kernel<<<gridE, TPB>>>(edge_index);
    scan_reduce_kernel<<<NBLK, SCAN_BLK>>>();           // also computes dinv
    scan_offsets_kernel<<<1, 256>>>();
    scan_write_kernel<<<NBLK, SCAN_BLK>>>();
    fill_kernel<<<gridE, TPB>>>(edge_index);

    // input projection
    in_proj_kernel<<<gridT, TPB>>>(x, W_in, b_in);

    // 3 GCN layers
    for (int i = 0; i < 3; i++) {
        gemm64_bf16_kernel<<<gridT, TPB>>>(d_h, conv_w + i * HID * HID, d_hwb);
        agg_kernel<<<gridW, TPB>>>(conv_b + i * HID,
                                   bn_gamma + i * HID, bn_beta + i * HID,
                                   bn_mean + i * HID, bn_var + i * HID);
    }

    // fused output MLP + residual
    out_fused_kernel<<<gridT, TPB>>>(d_h, W1, b1, W2, b2, x, out);
}

// round 8
// speedup vs baseline: 1.5064x; 1.5064x over previous
#include <cuda_runtime.h>
#include <cuda_bf16.h>

#define N_NODES 50000
#define N_EDGES 800000
#define HID 64
#define IN_DIM 4
#define BN_EPS 1e-5f

#define SCAN_BLK 256
#define NBLK ((N_NODES + SCAN_BLK - 1) / SCAN_BLK)   // 196
static_assert(NBLK <= 256, "NBLK must fit one scan block");

// ---------------- scratch (static device globals; no allocation) ----------------
// Symbols passed as kernel args from host MUST be resolved with
// cudaGetSymbolAddress (bare symbol = host shadow; ATS silently reads host BSS).
__device__ __align__(16) int   g_deg[N_NODES];
__device__ __align__(16) float g_dinv[N_NODES];
__device__ __align__(16) int   g_rowptr[N_NODES + 1];
__device__ __align__(16) int   g_cursor[N_NODES];
__device__ __align__(16) int2  g_srcw[N_EDGES];          // (src, w-bits)
__device__ __align__(16) float g_h[N_NODES * HID];       // fp32 residual stream
__device__ __align__(16) float g_hw[N_NODES * HID];      // fp32 message matrix
__device__ __align__(16) int   g_blocksum[NBLK];
__device__ __align__(16) int   g_blockoff[NBLK];

// ---------------- graph preprocessing ----------------
__global__ void zero_deg_kernel() {
    int i = blockIdx.x * blockDim.x + threadIdx.x;
    if (i < N_NODES) g_deg[i] = 0;
}

__global__ void count_deg_kernel(const int* __restrict__ edge_index) {
    int e = blockIdx.x * blockDim.x + threadIdx.x;
    if (e < N_EDGES) {
        int dst = edge_index[N_EDGES + e];   // row 1 of [2, E]
        atomicAdd(&g_deg[dst], 1);
    }
}

// stage 1: per-block tree reduction of degrees (+ fused dinv computation)
__global__ void scan_reduce_kernel() {
    __shared__ int sdata[SCAN_BLK];
    int b = blockIdx.x, t = threadIdx.x;
    int i = b * SCAN_BLK + t;
    int d = (i < N_NODES) ? g_deg[i] : 0;
    if (i < N_NODES) g_dinv[i] = rsqrtf((float)(d + 1));  // +1 self loop
    sdata[t] = d;
    __syncthreads();
    #pragma unroll
    for (int s = SCAN_BLK / 2; s > 0; s >>= 1) {
        if (t < s) sdata[t] += sdata[t + s];
        __syncthreads();
    }
    if (t == 0) g_blocksum[b] = sdata[0];
}

// stage 2: one block scans the block sums (double-buffered)
__global__ void scan_offsets_kernel() {
    __shared__ int buf[2][256];
    int t = threadIdx.x;
    buf[0][t] = (t < NBLK) ? g_blocksum[t] : 0;
    int cur = 0;
    __syncthreads();
    #pragma unroll
    for (int off = 1; off < 256; off <<= 1) {
        int x = buf[cur][t];
        if (t >= off) x += buf[cur][t - off];
        buf[1 - cur][t] = x;
        cur = 1 - cur;
        __syncthreads();
    }
    if (t < NBLK) g_blockoff[t] = (t > 0) ? buf[cur][t - 1] : 0;
    if (t == NBLK - 1) g_rowptr[N_NODES] = buf[cur][t];
}

// stage 3: per-block scan of degrees + write rowptr/cursor
__global__ void scan_write_kernel() {
    __shared__ int buf[2][SCAN_BLK];
    int b = blockIdx.x, t = threadIdx.x;
    int i = b * SCAN_BLK + t;
    int v = (i < N_NODES) ? g_deg[i] : 0;
    buf[0][t] = v;
    int cur = 0;
    __syncthreads();
    #pragma unroll
    for (int off = 1; off < SCAN_BLK; off <<= 1) {
        int x = buf[cur][t];
        if (t >= off) x += buf[cur][t - off];
        buf[1 - cur][t] = x;
        cur = 1 - cur;
        __syncthreads();
    }
    int incl = buf[cur][t];
    int excl = incl - v + g_blockoff[b];
    if (i < N_NODES) {
        g_rowptr[i] = excl;
        g_cursor[i] = excl;
    }
}

__global__ void fill_kernel(const int* __restrict__ edge_index) {
    int e = blockIdx.x * blockDim.x + threadIdx.x;
    if (e < N_EDGES) {
        int src = edge_index[e];
        int dst = edge_index[N_EDGES + e];
        int pos = atomicAdd(&g_cursor[dst], 1);
        float w = g_dinv[src] * g_dinv[dst];
        g_srcw[pos] = make_int2(src, __float_as_int(w));
    }
}

// ---------------- input projection: h = x @ W_in + b_in ----------------
__global__ void in_proj_kernel(const float* __restrict__ x,
                               const float* __restrict__ W_in,
                               const float* __restrict__ b_in) {
    __shared__ float xs[64 * IN_DIM];
    __shared__ float Ws[IN_DIM * HID];
    __shared__ float bs[HID];
    int tid = threadIdx.x;
    int n0 = blockIdx.x * 64;

    if (tid < IN_DIM * HID) Ws[tid] = W_in[tid];
    if (tid < HID) bs[tid] = b_in[tid];
    {
        int node = n0 + (tid >> 2);
        xs[tid] = (node < N_NODES) ? x[n0 * IN_DIM + tid] : 0.f;
    }
    __syncthreads();

    int j = tid & 63;
    int ng = tid >> 6;
    float bj = bs[j];
    float w0 = Ws[0 * HID + j], w1 = Ws[1 * HID + j], w2 = Ws[2 * HID + j], w3 = Ws[3 * HID + j];
    #pragma unroll 4
    for (int nn = 0; nn < 16; nn++) {
        int nloc = ng * 16 + nn;
        int node = n0 + nloc;
        if (node < N_NODES) {
            const float* xr = &xs[nloc * IN_DIM];
            g_h[node * HID + j] = bj + xr[0] * w0 + xr[1] * w1 + xr[2] * w2 + xr[3] * w3;
        }
    }
}

// ---------------- 64x64 GEMM: C = A @ W  (fp32 out) ----------------
// A, C are REAL device pointers (cudaGetSymbolAddress).
__global__ void gemm64_kernel(const float* __restrict__ A,
                              const float* __restrict__ W,
                              float* __restrict__ C) {
    __shared__ float hT[64 * 68];
    __shared__ float Ws[64 * 64];
    int tid = threadIdx.x;
    int n0 = blockIdx.x * 64;

    {
        const float4* W4 = (const float4*)W;
        float4* Ws4 = (float4*)Ws;
        #pragma unroll
        for (int i = tid; i < 1024; i += 256) Ws4[i] = W4[i];
    }
    {
        int nn = tid & 63;
        int kq4 = tid >> 6;
        int node = n0 + nn;
        const float4* A4 = (const float4*)A;
        #pragma unroll
        for (int q = 0; q < 4; q++) {
            int kq = kq4 * 4 + q;
            float4 hv = (node < N_NODES) ? A4[node * 16 + kq]
                                         : make_float4(0.f, 0.f, 0.f, 0.f);
            hT[(kq * 4 + 0) * 68 + nn] = hv.x;
            hT[(kq * 4 + 1) * 68 + nn] = hv.y;
            hT[(kq * 4 + 2) * 68 + nn] = hv.z;
            hT[(kq * 4 + 3) * 68 + nn] = hv.w;
        }
    }
    __syncthreads();

    int nq = tid & 15;
    int jq = tid >> 4;
    const float4* Ws4 = (const float4*)Ws;

    float4 acc0 = make_float4(0.f, 0.f, 0.f, 0.f);
    float4 acc1 = acc0, acc2 = acc0, acc3 = acc0;
    #pragma unroll
    for (int k = 0; k < 64; k++) {
        float4 wv = Ws4[k * 16 + jq];
        float4 hv = *(const float4*)&hT[k * 68 + nq * 4];
        acc0.x += hv.x * wv.x; acc0.y += hv.x * wv.y; acc0.z += hv.x * wv.z; acc0.w += hv.x * wv.w;
        acc1.x += hv.y * wv.x; acc1.y += hv.y * wv.y; acc1.z += hv.y * wv.z; acc1.w += hv.y * wv.w;
        acc2.x += hv.z * wv.x; acc2.y += hv.z * wv.y; acc2.z += hv.z * wv.z; acc2.w += hv.z * wv.w;
        acc3.x += hv.w * wv.x; acc3.y += hv.w * wv.y; acc3.z += hv.w * wv.z; acc3.w += hv.w * wv.w;
    }

    float4* C4 = (float4*)C;
    float4 accs[4] = {acc0, acc1, acc2, acc3};
    #pragma unroll
    for (int ni = 0; ni < 4; ni++) {
        int node = n0 + nq * 4 + ni;
        if (node < N_NODES) C4[node * 16 + jq] = accs[ni];
    }
}

// ---------------- aggregate + BN + ReLU + residual ----------------
// 16-lane group per node; lane covers 4 features as float4.
// Full 16-edge tiles are unrolled so ptxas batches the independent row loads.
__global__ void agg_kernel(const float* __restrict__ conv_b,
                           const float* __restrict__ bn_gamma,
                           const float* __restrict__ bn_beta,
                           const float* __restrict__ bn_mean,
                           const float* __restrict__ bn_var) {
    int gidx = (blockIdx.x * blockDim.x + threadIdx.x) >> 4;   // group = node
    int gl = threadIdx.x & 15;                                  // lane in group
    if (gidx >= N_NODES) return;
    int v = gidx;
    unsigned gmask = 0xFFFFu << (threadIdx.x & 16);             // this half-warp

    const float4* hw4 = (const float4*)g_hw;
    float4* h4 = (float4*)g_h;

    float dv = g_dinv[v];
    float wself = dv * dv;
    float4 sv = hw4[v * 16 + gl];
    float4 acc;
    acc.x = sv.x * wself; acc.y = sv.y * wself;
    acc.z = sv.z * wself; acc.w = sv.w * wself;

    int beg = g_rowptr[v];
    int end = g_rowptr[v + 1];
    int e = beg;
    // full tiles of 16 edges: fixed trip count -> unrolled, loads batched
    for (; e + 16 <= end; e += 16) {
        int2 p = g_srcw[e + gl];
        #pragma unroll
        for (int j = 0; j < 16; j++) {
            int s = __shfl_sync(gmask, p.x, j, 16);
            float w = __int_as_float(__shfl_sync(gmask, p.y, j, 16));
            float4 hv = hw4[s * 16 + gl];
            acc.x += hv.x * w; acc.y += hv.y * w;
            acc.z += hv.z * w; acc.w += hv.w * w;
        }
    }
    // remainder
    if (e < end) {
        int idx = e + gl;
        int2 p = (idx < end) ? g_srcw[idx] : make_int2(0, 0);
        int cnt = end - e;
        for (int j = 0; j < cnt; j++) {
            int s = __shfl_sync(gmask, p.x, j, 16);
            float w = __int_as_float(__shfl_sync(gmask, p.y, j, 16));
            float4 hv = hw4[s * 16 + gl];
            acc.x += hv.x * w; acc.y += hv.y * w;
            acc.z += hv.z * w; acc.w += hv.w * w;
        }
    }

    // fused epilogue: + conv_b, BN(eval), ReLU, + residual
    float4 cb = ((const float4*)conv_b)[gl];
    float4 gm = ((const float4*)bn_gamma)[gl];
    float4 bt = ((const float4*)bn_beta)[gl];
    float4 mn = ((const float4*)bn_mean)[gl];
    float4 vr = ((const float4*)bn_var)[gl];
    float4 o;
    o.x = fmaxf((acc.x + cb.x - mn.x) * (gm.x * rsqrtf(vr.x + BN_EPS)) + bt.x, 0.f);
    o.y = fmaxf((acc.y + cb.y - mn.y) * (gm.y * rsqrtf(vr.y + BN_EPS)) + bt.y, 0.f);
    o.z = fmaxf((acc.z + cb.z - mn.z) * (gm.z * rsqrtf(vr.z + BN_EPS)) + bt.z, 0.f);
    o.w = fmaxf((acc.w + cb.w - mn.w) * (gm.w * rsqrtf(vr.w + BN_EPS)) + bt.w, 0.f);
    float4 res = h4[v * 16 + gl];
    o.x += res.x; o.y += res.y; o.z += res.z; o.w += res.w;
    h4[v * 16 + gl] = o;
}

// ---------------- fused output MLP: out = x + relu(h@W1+b1)@W2 + b2 ----------------
__global__ void out_fused_kernel(const float* __restrict__ A,   // g_h (device ptr)
                                 const float* __restrict__ W1,
                                 const float* __restrict__ b1,
                                 const float* __restrict__ W2,
                                 const float* __restrict__ b2,
                                 const float* __restrict__ x,
                                 float* __restrict__ out) {
    __shared__ float hT[64 * 68];
    __shared__ float Ws[64 * 64];
    __shared__ float ts[64 * 68];
    __shared__ float W2s[HID * IN_DIM];
    __shared__ float b2s[IN_DIM];
    int tid = threadIdx.x;
    int n0 = blockIdx.x * 64;

    {
        const float4* W4 = (const float4*)W1;
        float4* Ws4 = (float4*)Ws;
        #pragma unroll
        for (int i = tid; i < 1024; i += 256) Ws4[i] = W4[i];
    }
    if (tid < HID * IN_DIM) W2s[tid] = W2[tid];
    if (tid < IN_DIM) b2s[tid] = b2[tid];
    {
        int nn = tid & 63;
        int kq4 = tid >> 6;
        int node = n0 + nn;
        const float4* A4 = (const float4*)A;
        #pragma unroll
        for (int q = 0; q < 4; q++) {
            int kq = kq4 * 4 + q;
            float4 hv = (node < N_NODES) ? A4[node * 16 + kq]
                                         : make_float4(0.f, 0.f, 0.f, 0.f);
            hT[(kq * 4 + 0) * 68 + nn] = hv.x;
            hT[(kq * 4 + 1) * 68 + nn] = hv.y;
            hT[(kq * 4 + 2) * 68 + nn] = hv.z;
            hT[(kq * 4 + 3) * 68 + nn] = hv.w;
        }
    }
    __syncthreads();

    int nq = tid & 15;
    int jq = tid >> 4;
    const float4* Ws4 = (const float4*)Ws;

    float4 acc0 = make_float4(0.f, 0.f, 0.f, 0.f);
    float4 acc1 = acc0, acc2 = acc0, acc3 = acc0;
    #pragma unroll
    for (int k = 0; k < 64; k++) {
        float4 wv = Ws4[k * 16 + jq];
        float4 hv = *(const float4*)&hT[k * 68 + nq * 4];
        acc0.x += hv.x * wv.x; acc0.y += hv.x * wv.y; acc0.z += hv.x * wv.z; acc0.w += hv.x * wv.w;
        acc1.x += hv.y * wv.x; acc1.y += hv.y * wv.y; acc1.z += hv.y * wv.z; acc1.w += hv.y * wv.w;
        acc2.x += hv.z * wv.x; acc2.y += hv.z * wv.y; acc2.z += hv.z * wv.z; acc2.w += hv.z * wv.w;
        acc3.x += hv.w * wv.x; acc3.y += hv.w * wv.y; acc3.z += hv.w * wv.z; acc3.w += hv.w * wv.w;
    }

    float4 bv = ((const float4*)b1)[jq];
    float4 accs[4] = {acc0, acc1, acc2, acc3};
    #pragma unroll
    for (int ni = 0; ni < 4; ni++) {
        int nloc = nq * 4 + ni;
        float4 r = accs[ni];
        r.x = fmaxf(r.x + bv.x, 0.f);
        r.y = fmaxf(r.y + bv.y, 0.f);
        r.z = fmaxf(r.z + bv.z, 0.f);
        r.w = fmaxf(r.w + bv.w, 0.f);
        *(float4*)&ts[nloc * 68 + jq * 4] = r;
    }
    __syncthreads();

    int nloc = tid >> 2;
    int m = tid & 3;
    int node = n0 + nloc;
    float acc = 0.f;
    #pragma unroll
    for (int l = 0; l < 64; l++) {
        acc += ts[nloc * 68 + l] * W2s[l * IN_DIM + m];
    }
    if (node < N_NODES) {
        out[node * IN_DIM + m] = x[node * IN_DIM + m] + b2s[m] + acc;
    }
}

// ---------------- launch ----------------
extern "C" void kernel_launch(void* const* d_in, const int* in_sizes, int n_in,
                              void* d_out, int out_size) {
    const float* x          = (const float*)d_in[0];
    const int*   edge_index = (const int*)d_in[1];
    const float* W_in       = (const float*)d_in[2];
    const float* b_in       = (const float*)d_in[3];
    const float* conv_w     = (const float*)d_in[4];   // [3,64,64]
    const float* conv_b     = (const float*)d_in[5];   // [3,64]
    const float* bn_gamma   = (const float*)d_in[6];
    const float* bn_beta    = (const float*)d_in[7];
    const float* bn_mean    = (const float*)d_in[8];
    const float* bn_var     = (const float*)d_in[9];
    const float* W1         = (const float*)d_in[10];
    const float* b1         = (const float*)d_in[11];
    const float* W2         = (const float*)d_in[12];
    const float* b2         = (const float*)d_in[13];
    float* out = (float*)d_out;

    void* p_h = nullptr;
    void* p_hw = nullptr;
    cudaGetSymbolAddress(&p_h, g_h);
    cudaGetSymbolAddress(&p_hw, g_hw);
    float* d_h = (float*)p_h;
    float* d_hw = (float*)p_hw;

    const int TPB = 256;
    const int gridN = (N_NODES + TPB - 1) / TPB;
    const int gridE = (N_EDGES + TPB - 1) / TPB;
    const int gridT = (N_NODES + 63) / 64;
    const int gridG = (N_NODES * 16 + TPB - 1) / TPB;   // 16-lane group per node

    // build graph structure
    zero_deg_kernel<<<gridN, TPB>>>();
    count_deg_kernel<<<gridE, TPB>>>(edge_index);
    scan_reduce_kernel<<<NBLK, SCAN_BLK>>>();           // also computes dinv
    scan_offsets_kernel<<<1, 256>>>();
    scan_write_kernel<<<NBLK, SCAN_BLK>>>();
    fill_kernel<<<gridE, TPB>>>(edge_index);

    // input projection
    in_proj_kernel<<<gridT, TPB>>>(x, W_in, b_in);

    // 3 GCN layers
    for (int i = 0; i < 3; i++) {
        gemm64_kernel<<<gridT, TPB>>>(d_h, conv_w + i * HID * HID, d_hw);
        agg_kernel<<<gridG, TPB>>>(conv_b + i * HID,
                                   bn_gamma + i * HID, bn_beta + i * HID,
                                   bn_mean + i * HID, bn_var + i * HID);
    }

    // fused output MLP + residual
    out_fused_kernel<<<gridT, TPB>>>(d_h, W1, b1, W2, b2, x, out);
}

// round 9
// speedup vs baseline: 1.5378x; 1.0208x over previous
#include <cuda_runtime.h>
#include <cuda_bf16.h>

#define N_NODES 50000
#define N_EDGES 800000
#define HID 64
#define IN_DIM 4
#define BN_EPS 1e-5f

#define SCAN_BLK 256
#define NBLK ((N_NODES + SCAN_BLK - 1) / SCAN_BLK)   // 196
static_assert(NBLK <= 256, "NBLK must fit one scan block");

// ---------------- scratch (static device globals; no allocation) ----------------
// Symbols passed as kernel args from host MUST be resolved with
// cudaGetSymbolAddress (bare symbol = host shadow; ATS silently reads host BSS).
__device__ __align__(16) int   g_deg[N_NODES];
__device__ __align__(16) float g_dinv[N_NODES];
__device__ __align__(16) int   g_rowptr[N_NODES + 1];
__device__ __align__(16) int   g_cursor[N_NODES];
__device__ __align__(16) int2  g_srcw[N_EDGES];          // (src, w-bits)
__device__ __align__(16) float g_h[N_NODES * HID];       // fp32 residual stream
__device__ __align__(16) uint2 g_hwb[N_NODES * 16];      // bf16 message matrix: 16 x bf16x4 per row
__device__ __align__(16) int   g_blocksum[NBLK];
__device__ __align__(16) int   g_blockoff[NBLK];

// ---------------- graph preprocessing ----------------
__global__ void zero_deg_kernel() {
    int i = blockIdx.x * blockDim.x + threadIdx.x;
    if (i < N_NODES) g_deg[i] = 0;
}

__global__ void count_deg_kernel(const int* __restrict__ edge_index) {
    int e = blockIdx.x * blockDim.x + threadIdx.x;
    if (e < N_EDGES) {
        int dst = edge_index[N_EDGES + e];   // row 1 of [2, E]
        atomicAdd(&g_deg[dst], 1);
    }
}

// stage 1: per-block tree reduction of degrees (+ fused dinv computation)
__global__ void scan_reduce_kernel() {
    __shared__ int sdata[SCAN_BLK];
    int b = blockIdx.x, t = threadIdx.x;
    int i = b * SCAN_BLK + t;
    int d = (i < N_NODES) ? g_deg[i] : 0;
    if (i < N_NODES) g_dinv[i] = rsqrtf((float)(d + 1));  // +1 self loop
    sdata[t] = d;
    __syncthreads();
    #pragma unroll
    for (int s = SCAN_BLK / 2; s > 0; s >>= 1) {
        if (t < s) sdata[t] += sdata[t + s];
        __syncthreads();
    }
    if (t == 0) g_blocksum[b] = sdata[0];
}

// stage 2: one block scans the block sums (double-buffered)
__global__ void scan_offsets_kernel() {
    __shared__ int buf[2][256];
    int t = threadIdx.x;
    buf[0][t] = (t < NBLK) ? g_blocksum[t] : 0;
    int cur = 0;
    __syncthreads();
    #pragma unroll
    for (int off = 1; off < 256; off <<= 1) {
        int x = buf[cur][t];
        if (t >= off) x += buf[cur][t - off];
        buf[1 - cur][t] = x;
        cur = 1 - cur;
        __syncthreads();
    }
    if (t < NBLK) g_blockoff[t] = (t > 0) ? buf[cur][t - 1] : 0;
    if (t == NBLK - 1) g_rowptr[N_NODES] = buf[cur][t];
}

// stage 3: per-block scan of degrees + write rowptr/cursor
__global__ void scan_write_kernel() {
    __shared__ int buf[2][SCAN_BLK];
    int b = blockIdx.x, t = threadIdx.x;
    int i = b * SCAN_BLK + t;
    int v = (i < N_NODES) ? g_deg[i] : 0;
    buf[0][t] = v;
    int cur = 0;
    __syncthreads();
    #pragma unroll
    for (int off = 1; off < SCAN_BLK; off <<= 1) {
        int x = buf[cur][t];
        if (t >= off) x += buf[cur][t - off];
        buf[1 - cur][t] = x;
        cur = 1 - cur;
        __syncthreads();
    }
    int incl = buf[cur][t];
    int excl = incl - v + g_blockoff[b];
    if (i < N_NODES) {
        g_rowptr[i] = excl;
        g_cursor[i] = excl;
    }
}

__global__ void fill_kernel(const int* __restrict__ edge_index) {
    int e = blockIdx.x * blockDim.x + threadIdx.x;
    if (e < N_EDGES) {
        int src = edge_index[e];
        int dst = edge_index[N_EDGES + e];
        int pos = atomicAdd(&g_cursor[dst], 1);
        float w = g_dinv[src] * g_dinv[dst];
        g_srcw[pos] = make_int2(src, __float_as_int(w));
    }
}

// ---------------- input projection: h = x @ W_in + b_in ----------------
__global__ void in_proj_kernel(const float* __restrict__ x,
                               const float* __restrict__ W_in,
                               const float* __restrict__ b_in) {
    __shared__ float xs[64 * IN_DIM];
    __shared__ float Ws[IN_DIM * HID];
    __shared__ float bs[HID];
    int tid = threadIdx.x;
    int n0 = blockIdx.x * 64;

    if (tid < IN_DIM * HID) Ws[tid] = W_in[tid];
    if (tid < HID) bs[tid] = b_in[tid];
    {
        int node = n0 + (tid >> 2);
        xs[tid] = (node < N_NODES) ? x[n0 * IN_DIM + tid] : 0.f;
    }
    __syncthreads();

    int j = tid & 63;
    int ng = tid >> 6;
    float bj = bs[j];
    float w0 = Ws[0 * HID + j], w1 = Ws[1 * HID + j], w2 = Ws[2 * HID + j], w3 = Ws[3 * HID + j];
    #pragma unroll 4
    for (int nn = 0; nn < 16; nn++) {
        int nloc = ng * 16 + nn;
        int node = n0 + nloc;
        if (node < N_NODES) {
            const float* xr = &xs[nloc * IN_DIM];
            g_h[node * HID + j] = bj + xr[0] * w0 + xr[1] * w1 + xr[2] * w2 + xr[3] * w3;
        }
    }
}

// ---------------- 64x64 GEMM: hwb = bf16(A @ W) ----------------
// A, C are REAL device pointers (cudaGetSymbolAddress).
__global__ void gemm64_bf16_kernel(const float* __restrict__ A,
                                   const float* __restrict__ W,
                                   uint2* __restrict__ C) {
    __shared__ float hT[64 * 68];
    __shared__ float Ws[64 * 64];
    int tid = threadIdx.x;
    int n0 = blockIdx.x * 64;

    {
        const float4* W4 = (const float4*)W;
        float4* Ws4 = (float4*)Ws;
        #pragma unroll
        for (int i = tid; i < 1024; i += 256) Ws4[i] = W4[i];
    }
    {
        int nn = tid & 63;
        int kq4 = tid >> 6;
        int node = n0 + nn;
        const float4* A4 = (const float4*)A;
        #pragma unroll
        for (int q = 0; q < 4; q++) {
            int kq = kq4 * 4 + q;
            float4 hv = (node < N_NODES) ? A4[node * 16 + kq]
                                         : make_float4(0.f, 0.f, 0.f, 0.f);
            hT[(kq * 4 + 0) * 68 + nn] = hv.x;
            hT[(kq * 4 + 1) * 68 + nn] = hv.y;
            hT[(kq * 4 + 2) * 68 + nn] = hv.z;
            hT[(kq * 4 + 3) * 68 + nn] = hv.w;
        }
    }
    __syncthreads();

    int nq = tid & 15;
    int jq = tid >> 4;
    const float4* Ws4 = (const float4*)Ws;

    float4 acc0 = make_float4(0.f, 0.f, 0.f, 0.f);
    float4 acc1 = acc0, acc2 = acc0, acc3 = acc0;
    #pragma unroll
    for (int k = 0; k < 64; k++) {
        float4 wv = Ws4[k * 16 + jq];
        float4 hv = *(const float4*)&hT[k * 68 + nq * 4];
        acc0.x += hv.x * wv.x; acc0.y += hv.x * wv.y; acc0.z += hv.x * wv.z; acc0.w += hv.x * wv.w;
        acc1.x += hv.y * wv.x; acc1.y += hv.y * wv.y; acc1.z += hv.y * wv.z; acc1.w += hv.y * wv.w;
        acc2.x += hv.z * wv.x; acc2.y += hv.z * wv.y; acc2.z += hv.z * wv.z; acc2.w += hv.z * wv.w;
        acc3.x += hv.w * wv.x; acc3.y += hv.w * wv.y; acc3.z += hv.w * wv.z; acc3.w += hv.w * wv.w;
    }

    float4 accs[4] = {acc0, acc1, acc2, acc3};
    #pragma unroll
    for (int ni = 0; ni < 4; ni++) {
        int node = n0 + nq * 4 + ni;
        if (node < N_NODES) {
            float4 r = accs[ni];
            __nv_bfloat162 lo = __floats2bfloat162_rn(r.x, r.y);
            __nv_bfloat162 hi = __floats2bfloat162_rn(r.z, r.w);
            uint2 pk;
            pk.x = *(unsigned int*)&lo;
            pk.y = *(unsigned int*)&hi;
            C[node * 16 + jq] = pk;   // row = 64 bf16 = 16 uint2
        }
    }
}

// ---------------- aggregate + BN + ReLU + residual ----------------
// 16-lane group per node; lane covers 4 features (bf16x4 = uint2 load).
// Full 16-edge tiles unrolled so ptxas batches the independent row loads.
__global__ void agg_kernel(const float* __restrict__ conv_b,
                           const float* __restrict__ bn_gamma,
                           const float* __restrict__ bn_beta,
                           const float* __restrict__ bn_mean,
                           const float* __restrict__ bn_var) {
    int gidx = (blockIdx.x * blockDim.x + threadIdx.x) >> 4;   // group = node
    int gl = threadIdx.x & 15;                                  // lane in group
    if (gidx >= N_NODES) return;
    int v = gidx;
    unsigned gmask = 0xFFFFu << (threadIdx.x & 16);             // this half-warp

    float4* h4 = (float4*)g_h;

    float dv = g_dinv[v];
    float wself = dv * dv;
    float4 acc;
    {
        uint2 pk = g_hwb[v * 16 + gl];
        float2 lo = __bfloat1622float2(*(__nv_bfloat162*)&pk.x);
        float2 hi = __bfloat1622float2(*(__nv_bfloat162*)&pk.y);
        acc.x = lo.x * wself; acc.y = lo.y * wself;
        acc.z = hi.x * wself; acc.w = hi.y * wself;
    }

    int beg = g_rowptr[v];
    int end = g_rowptr[v + 1];
    int e = beg;
    // full tiles of 16 edges: fixed trip count -> unrolled, loads batched
    for (; e + 16 <= end; e += 16) {
        int2 p = g_srcw[e + gl];
        #pragma unroll
        for (int j = 0; j < 16; j++) {
            int s = __shfl_sync(gmask, p.x, j, 16);
            float w = __int_as_float(__shfl_sync(gmask, p.y, j, 16));
            uint2 pk = g_hwb[s * 16 + gl];
            float2 lo = __bfloat1622float2(*(__nv_bfloat162*)&pk.x);
            float2 hi = __bfloat1622float2(*(__nv_bfloat162*)&pk.y);
            acc.x += lo.x * w; acc.y += lo.y * w;
            acc.z += hi.x * w; acc.w += hi.y * w;
        }
    }
    // remainder
    if (e < end) {
        int idx = e + gl;
        int2 p = (idx < end) ? g_srcw[idx] : make_int2(0, 0);
        int cnt = end - e;
        for (int j = 0; j < cnt; j++) {
            int s = __shfl_sync(gmask, p.x, j, 16);
            float w = __int_as_float(__shfl_sync(gmask, p.y, j, 16));
            uint2 pk = g_hwb[s * 16 + gl];
            float2 lo = __bfloat1622float2(*(__nv_bfloat162*)&pk.x);
            float2 hi = __bfloat1622float2(*(__nv_bfloat162*)&pk.y);
            acc.x += lo.x * w; acc.y += lo.y * w;
            acc.z += hi.x * w; acc.w += hi.y * w;
        }
    }

    // fused epilogue: + conv_b, BN(eval), ReLU, + residual
    float4 cb = ((const float4*)conv_b)[gl];
    float4 gm = ((const float4*)bn_gamma)[gl];
    float4 bt = ((const float4*)bn_beta)[gl];
    float4 mn = ((const float4*)bn_mean)[gl];
    float4 vr = ((const float4*)bn_var)[gl];
    float4 o;
    o.x = fmaxf((acc.x + cb.x - mn.x) * (gm.x * rsqrtf(vr.x + BN_EPS)) + bt.x, 0.f);
    o.y = fmaxf((acc.y + cb.y - mn.y) * (gm.y * rsqrtf(vr.y + BN_EPS)) + bt.y, 0.f);
    o.z = fmaxf((acc.z + cb.z - mn.z) * (gm.z * rsqrtf(vr.z + BN_EPS)) + bt.z, 0.f);
    o.w = fmaxf((acc.w + cb.w - mn.w) * (gm.w * rsqrtf(vr.w + BN_EPS)) + bt.w, 0.f);
    float4 res = h4[v * 16 + gl];
    o.x += res.x; o.y += res.y; o.z += res.z; o.w += res.w;
    h4[v * 16 + gl] = o;
}

// ---------------- fused output MLP: out = x + relu(h@W1+b1)@W2 + b2 ----------------
__global__ void out_fused_kernel(const float* __restrict__ A,   // g_h (device ptr)
                                 const float* __restrict__ W1,
                                 const float* __restrict__ b1,
                                 const float* __restrict__ W2,
                                 const float* __restrict__ b2,
                                 const float* __restrict__ x,
                                 float* __restrict__ out) {
    __shared__ float hT[64 * 68];
    __shared__ float Ws[64 * 64];
    __shared__ float ts[64 * 68];
    __shared__ float W2s[HID * IN_DIM];
    __shared__ float b2s[IN_DIM];
    int tid = threadIdx.x;
    int n0 = blockIdx.x * 64;

    {
        const float4* W4 = (const float4*)W1;
        float4* Ws4 = (float4*)Ws;
        #pragma unroll
        for (int i = tid; i < 1024; i += 256) Ws4[i] = W4[i];
    }
    if (tid < HID * IN_DIM) W2s[tid] = W2[tid];
    if (tid < IN_DIM) b2s[tid] = b2[tid];
    {
        int nn = tid & 63;
        int kq4 = tid >> 6;
        int node = n0 + nn;
        const float4* A4 = (const float4*)A;
        #pragma unroll
        for (int q = 0; q < 4; q++) {
            int kq = kq4 * 4 + q;
            float4 hv = (node < N_NODES) ? A4[node * 16 + kq]
                                         : make_float4(0.f, 0.f, 0.f, 0.f);
            hT[(kq * 4 + 0) * 68 + nn] = hv.x;
            hT[(kq * 4 + 1) * 68 + nn] = hv.y;
            hT[(kq * 4 + 2) * 68 + nn] = hv.z;
            hT[(kq * 4 + 3) * 68 + nn] = hv.w;
        }
    }
    __syncthreads();

    int nq = tid & 15;
    int jq = tid >> 4;
    const float4* Ws4 = (const float4*)Ws;

    float4 acc0 = make_float4(0.f, 0.f, 0.f, 0.f);
    float4 acc1 = acc0, acc2 = acc0, acc3 = acc0;
    #pragma unroll
    for (int k = 0; k < 64; k++) {
        float4 wv = Ws4[k * 16 + jq];
        float4 hv = *(const float4*)&hT[k * 68 + nq * 4];
        acc0.x += hv.x * wv.x; acc0.y += hv.x * wv.y; acc0.z += hv.x * wv.z; acc0.w += hv.x * wv.w;
        acc1.x += hv.y * wv.x; acc1.y += hv.y * wv.y; acc1.z += hv.y * wv.z; acc1.w += hv.y * wv.w;
        acc2.x += hv.z * wv.x; acc2.y += hv.z * wv.y; acc2.z += hv.z * wv.z; acc2.w += hv.z * wv.w;
        acc3.x += hv.w * wv.x; acc3.y += hv.w * wv.y; acc3.z += hv.w * wv.z; acc3.w += hv.w * wv.w;
    }

    float4 bv = ((const float4*)b1)[jq];
    float4 accs[4] = {acc0, acc1, acc2, acc3};
    #pragma unroll
    for (int ni = 0; ni < 4; ni++) {
        int nloc = nq * 4 + ni;
        float4 r = accs[ni];
        r.x = fmaxf(r.x + bv.x, 0.f);
        r.y = fmaxf(r.y + bv.y, 0.f);
        r.z = fmaxf(r.z + bv.z, 0.f);
        r.w = fmaxf(r.w + bv.w, 0.f);
        *(float4*)&ts[nloc * 68 + jq * 4] = r;
    }
    __syncthreads();

    int nloc = tid >> 2;
    int m = tid & 3;
    int node = n0 + nloc;
    float acc = 0.f;
    #pragma unroll
    for (int l = 0; l < 64; l++) {
        acc += ts[nloc * 68 + l] * W2s[l * IN_DIM + m];
    }
    if (node < N_NODES) {
        out[node * IN_DIM + m] = x[node * IN_DIM + m] + b2s[m] + acc;
    }
}

// ---------------- launch ----------------
extern "C" void kernel_launch(void* const* d_in, const int* in_sizes, int n_in,
                              void* d_out, int out_size) {
    const float* x          = (const float*)d_in[0];
    const int*   edge_index = (const int*)d_in[1];
    const float* W_in       = (const float*)d_in[2];
    const float* b_in       = (const float*)d_in[3];
    const float* conv_w     = (const float*)d_in[4];   // [3,64,64]
    const float* conv_b     = (const float*)d_in[5];   // [3,64]
    const float* bn_gamma   = (const float*)d_in[6];
    const float* bn_beta    = (const float*)d_in[7];
    const float* bn_mean    = (const float*)d_in[8];
    const float* bn_var     = (const float*)d_in[9];
    const float* W1         = (const float*)d_in[10];
    const float* b1         = (const float*)d_in[11];
    const float* W2         = (const float*)d_in[12];
    const float* b2         = (const float*)d_in[13];
    float* out = (float*)d_out;

    void* p_h = nullptr;
    void* p_hwb = nullptr;
    cudaGetSymbolAddress(&p_h, g_h);
    cudaGetSymbolAddress(&p_hwb, g_hwb);
    float* d_h = (float*)p_h;
    uint2* d_hwb = (uint2*)p_hwb;

    const int TPB = 256;
    const int gridN = (N_NODES + TPB - 1) / TPB;
    const int gridE = (N_EDGES + TPB - 1) / TPB;
    const int gridT = (N_NODES + 63) / 64;
    const int gridG = (N_NODES * 16 + TPB - 1) / TPB;   // 16-lane group per node

    // build graph structure
    zero_deg_kernel<<<gridN, TPB>>>();
    count_deg_kernel<<<gridE, TPB>>>(edge_index);
    scan_reduce_kernel<<<NBLK, SCAN_BLK>>>();           // also computes dinv
    scan_offsets_kernel<<<1, 256>>>();
    scan_write_kernel<<<NBLK, SCAN_BLK>>>();
    fill_kernel<<<gridE, TPB>>>(edge_index);

    // input projection
    in_proj_kernel<<<gridT, TPB>>>(x, W_in, b_in);

    // 3 GCN layers
    for (int i = 0; i < 3; i++) {
        gemm64_bf16_kernel<<<gridT, TPB>>>(d_h, conv_w + i * HID * HID, d_hwb);
        agg_kernel<<<gridG, TPB>>>(conv_b + i * HID,
                                   bn_gamma + i * HID, bn_beta + i * HID,
                                   bn_mean + i * HID, bn_var + i * HID);
    }

    // fused output MLP + residual
    out_fused_kernel<<<gridT, TPB>>>(d_h, W1, b1, W2, b2, x, out);
}

// round 11
// speedup vs baseline: 1.5630x; 1.0164x over previous
#include <cuda_runtime.h>
#include <cuda_bf16.h>

#define N_NODES 50000
#define N_EDGES 800000
#define HID 64
#define IN_DIM 4
#define BN_EPS 1e-5f

#define SCAN_BLK 256
#define NBLK ((N_NODES + SCAN_BLK - 1) / SCAN_BLK)   // 196
static_assert(NBLK <= 256, "NBLK must fit one scan block");
static_assert(N_NODES < 65536, "src must fit in 16 bits");

// ---------------- scratch (static device globals; no allocation) ----------------
// Symbols passed as kernel args from host MUST be resolved with
// cudaGetSymbolAddress (bare symbol = host shadow; ATS silently reads host BSS).
__device__ __align__(16) int      g_deg[N_NODES];        // zeroed by fill_kernel for next replay
__device__ __align__(16) float    g_dinv[N_NODES];
__device__ __align__(16) int      g_rowptr[N_NODES + 1];
__device__ __align__(16) int      g_cursor[N_NODES];
__device__ __align__(16) unsigned g_sw[N_EDGES];         // src<<16 | bf16(w)
__device__ __align__(16) float    g_h[N_NODES * HID];    // fp32 residual stream
__device__ __align__(16) uint2    g_hwb[N_NODES * 16];   // bf16 message matrix: 16 x bf16x4 per row
__device__ __align__(16) int      g_blocksum[NBLK];
__device__ __align__(16) int      g_blockoff[NBLK];

// ---------------- graph preprocessing ----------------
__global__ void count_deg_kernel(const int* __restrict__ edge_index) {
    int e = blockIdx.x * blockDim.x + threadIdx.x;
    if (e < N_EDGES) {
        int dst = edge_index[N_EDGES + e];   // row 1 of [2, E]
        atomicAdd(&g_deg[dst], 1);
    }
}

// stage 1: per-block tree reduction of degrees (+ fused dinv computation)
__global__ void scan_reduce_kernel() {
    __shared__ int sdata[SCAN_BLK];
    int b = blockIdx.x, t = threadIdx.x;
    int i = b * SCAN_BLK + t;
    int d = (i < N_NODES) ? g_deg[i] : 0;
    if (i < N_NODES) g_dinv[i] = rsqrtf((float)(d + 1));  // +1 self loop
    sdata[t] = d;
    __syncthreads();
    #pragma unroll
    for (int s = SCAN_BLK / 2; s > 0; s >>= 1) {
        if (t < s) sdata[t] += sdata[t + s];
        __syncthreads();
    }
    if (t == 0) g_blocksum[b] = sdata[0];
}

// stage 2: one block scans the block sums (double-buffered)
__global__ void scan_offsets_kernel() {
    __shared__ int buf[2][256];
    int t = threadIdx.x;
    buf[0][t] = (t < NBLK) ? g_blocksum[t] : 0;
    int cur = 0;
    __syncthreads();
    #pragma unroll
    for (int off = 1; off < 256; off <<= 1) {
        int x = buf[cur][t];
        if (t >= off) x += buf[cur][t - off];
        buf[1 - cur][t] = x;
        cur = 1 - cur;
        __syncthreads();
    }
    if (t < NBLK) g_blockoff[t] = (t > 0) ? buf[cur][t - 1] : 0;
    if (t == NBLK - 1) g_rowptr[N_NODES] = buf[cur][t];
}

// stage 3: per-block scan of degrees + write rowptr/cursor
__global__ void scan_write_kernel() {
    __shared__ int buf[2][SCAN_BLK];
    int b = blockIdx.x, t = threadIdx.x;
    int i = b * SCAN_BLK + t;
    int v = (i < N_NODES) ? g_deg[i] : 0;
    buf[0][t] = v;
    int cur = 0;
    __syncthreads();
    #pragma unroll
    for (int off = 1; off < SCAN_BLK; off <<= 1) {
        int x = buf[cur][t];
        if (t >= off) x += buf[cur][t - off];
        buf[1 - cur][t] = x;
        cur = 1 - cur;
        __syncthreads();
    }
    int incl = buf[cur][t];
    int excl = incl - v + g_blockoff[b];
    if (i < N_NODES) {
        g_rowptr[i] = excl;
        g_cursor[i] = excl;
    }
}

// fill CSR; also re-zero g_deg for the next graph replay (deg is dead after scan_write)
__global__ void fill_kernel(const int* __restrict__ edge_index) {
    int e = blockIdx.x * blockDim.x + threadIdx.x;
    if (e < N_EDGES) {
        int src = edge_index[e];
        int dst = edge_index[N_EDGES + e];
        int pos = atomicAdd(&g_cursor[dst], 1);
        float w = g_dinv[src] * g_dinv[dst];
        unsigned short wb = __bfloat16_as_ushort(__float2bfloat16(w));
        g_sw[pos] = ((unsigned)src << 16) | (unsigned)wb;
    }
    if (e < N_NODES) g_deg[e] = 0;
}

// ---------------- input projection: h = x @ W_in + b_in ----------------
__global__ void in_proj_kernel(const float* __restrict__ x,
                               const float* __restrict__ W_in,
                               const float* __restrict__ b_in) {
    __shared__ float xs[64 * IN_DIM];
    __shared__ float Ws[IN_DIM * HID];
    __shared__ float bs[HID];
    int tid = threadIdx.x;
    int n0 = blockIdx.x * 64;

    if (tid < IN_DIM * HID) Ws[tid] = W_in[tid];
    if (tid < HID) bs[tid] = b_in[tid];
    {
        int node = n0 + (tid >> 2);
        xs[tid] = (node < N_NODES) ? x[n0 * IN_DIM + tid] : 0.f;
    }
    __syncthreads();

    int j = tid & 63;
    int ng = tid >> 6;
    float bj = bs[j];
    float w0 = Ws[0 * HID + j], w1 = Ws[1 * HID + j], w2 = Ws[2 * HID + j], w3 = Ws[3 * HID + j];
    #pragma unroll 4
    for (int nn = 0; nn < 16; nn++) {
        int nloc = ng * 16 + nn;
        int node = n0 + nloc;
        if (node < N_NODES) {
            const float* xr = &xs[nloc * IN_DIM];
            g_h[node * HID + j] = bj + xr[0] * w0 + xr[1] * w1 + xr[2] * w2 + xr[3] * w3;
        }
    }
}

// ---------------- 64x64 GEMM: hwb = bf16(A @ W) ----------------
// A, C are REAL device pointers (cudaGetSymbolAddress).
__global__ void gemm64_bf16_kernel(const float* __restrict__ A,
                                   const float* __restrict__ W,
                                   uint2* __restrict__ C) {
    __shared__ float hT[64 * 68];
    __shared__ float Ws[64 * 64];
    int tid = threadIdx.x;
    int n0 = blockIdx.x * 64;

    {
        const float4* W4 = (const float4*)W;
        float4* Ws4 = (float4*)Ws;
        #pragma unroll
        for (int i = tid; i < 1024; i += 256) Ws4[i] = W4[i];
    }
    {
        int nn = tid & 63;
        int kq4 = tid >> 6;
        int node = n0 + nn;
        const float4* A4 = (const float4*)A;
        #pragma unroll
        for (int q = 0; q < 4; q++) {
            int kq = kq4 * 4 + q;
            float4 hv = (node < N_NODES) ? A4[node * 16 + kq]
                                         : make_float4(0.f, 0.f, 0.f, 0.f);
            hT[(kq * 4 + 0) * 68 + nn] = hv.x;
            hT[(kq * 4 + 1) * 68 + nn] = hv.y;
            hT[(kq * 4 + 2) * 68 + nn] = hv.z;
            hT[(kq * 4 + 3) * 68 + nn] = hv.w;
        }
    }
    __syncthreads();

    int nq = tid & 15;
    int jq = tid >> 4;
    const float4* Ws4 = (const float4*)Ws;

    float4 acc0 = make_float4(0.f, 0.f, 0.f, 0.f);
    float4 acc1 = acc0, acc2 = acc0, acc3 = acc0;
    #pragma unroll
    for (int k = 0; k < 64; k++) {
        float4 wv = Ws4[k * 16 + jq];
        float4 hv = *(const float4*)&hT[k * 68 + nq * 4];
        acc0.x += hv.x * wv.x; acc0.y += hv.x * wv.y; acc0.z += hv.x * wv.z; acc0.w += hv.x * wv.w;
        acc1.x += hv.y * wv.x; acc1.y += hv.y * wv.y; acc1.z += hv.y * wv.z; acc1.w += hv.y * wv.w;
        acc2.x += hv.z * wv.x; acc2.y += hv.z * wv.y; acc2.z += hv.z * wv.z; acc2.w += hv.z * wv.w;
        acc3.x += hv.w * wv.x; acc3.y += hv.w * wv.y; acc3.z += hv.w * wv.z; acc3.w += hv.w * wv.w;
    }

    float4 accs[4] = {acc0, acc1, acc2, acc3};
    #pragma unroll
    for (int ni = 0; ni < 4; ni++) {
        int node = n0 + nq * 4 + ni;
        if (node < N_NODES) {
            float4 r = accs[ni];
            __nv_bfloat162 lo = __floats2bfloat162_rn(r.x, r.y);
            __nv_bfloat162 hi = __floats2bfloat162_rn(r.z, r.w);
            uint2 pk;
            pk.x = *(unsigned int*)&lo;
            pk.y = *(unsigned int*)&hi;
            C[node * 16 + jq] = pk;   // row = 64 bf16 = 16 uint2
        }
    }
}

// ---------------- aggregate + BN + ReLU + residual ----------------
// 16-lane group per node; lane covers 4 features (bf16x4 = uint2 load).
// Packed edge word: src<<16 | bf16(w)  -> ONE shfl per edge.
__global__ void agg_kernel(const float* __restrict__ conv_b,
                           const float* __restrict__ bn_gamma,
                           const float* __restrict__ bn_beta,
                           const float* __restrict__ bn_mean,
                           const float* __restrict__ bn_var) {
    int gidx = (blockIdx.x * blockDim.x + threadIdx.x) >> 4;   // group = node
    int gl = threadIdx.x & 15;                                  // lane in group
    if (gidx >= N_NODES) return;
    int v = gidx;
    unsigned gmask = 0xFFFFu << (threadIdx.x & 16);             // this half-warp

    float4* h4 = (float4*)g_h;

    float dv = g_dinv[v];
    float wself = dv * dv;
    float4 acc;
    {
        uint2 pk = g_hwb[v * 16 + gl];
        float2 lo = __bfloat1622float2(*(__nv_bfloat162*)&pk.x);
        float2 hi = __bfloat1622float2(*(__nv_bfloat162*)&pk.y);
        acc.x = lo.x * wself; acc.y = lo.y * wself;
        acc.z = hi.x * wself; acc.w = hi.y * wself;
    }

    int beg = g_rowptr[v];
    int end = g_rowptr[v + 1];
    int e = beg;
    // full tiles of 16 edges: fixed trip count -> unrolled, loads batched
    for (; e + 16 <= end; e += 16) {
        unsigned p = g_sw[e + gl];
        #pragma unroll
        for (int j = 0; j < 16; j++) {
            unsigned u = __shfl_sync(gmask, p, j, 16);
            int s = (int)(u >> 16);
            float w = __bfloat162float(__ushort_as_bfloat16((unsigned short)(u & 0xFFFFu)));
            uint2 pk = g_hwb[s * 16 + gl];
            float2 lo = __bfloat1622float2(*(__nv_bfloat162*)&pk.x);
            float2 hi = __bfloat1622float2(*(__nv_bfloat162*)&pk.y);
            acc.x += lo.x * w; acc.y += lo.y * w;
            acc.z += hi.x * w; acc.w += hi.y * w;
        }
    }
    // remainder
    if (e < end) {
        int idx = e + gl;
        unsigned p = (idx < end) ? g_sw[idx] : 0u;
        int cnt = end - e;
        for (int j = 0; j < cnt; j++) {
            unsigned u = __shfl_sync(gmask, p, j, 16);
            int s = (int)(u >> 16);
            float w = __bfloat162float(__ushort_as_bfloat16((unsigned short)(u & 0xFFFFu)));
            uint2 pk = g_hwb[s * 16 + gl];
            float2 lo = __bfloat1622float2(*(__nv_bfloat162*)&pk.x);
            float2 hi = __bfloat1622float2(*(__nv_bfloat162*)&pk.y);
            acc.x += lo.x * w; acc.y += lo.y * w;
            acc.z += hi.x * w; acc.w += hi.y * w;
        }
    }

    // fused epilogue: + conv_b, BN(eval), ReLU, + residual
    float4 cb = ((const float4*)conv_b)[gl];
    float4 gm = ((const float4*)bn_gamma)[gl];
    float4 bt = ((const float4*)bn_beta)[gl];
    float4 mn = ((const float4*)bn_mean)[gl];
    float4 vr = ((const float4*)bn_var)[gl];
    float4 o;
    o.x = fmaxf((acc.x + cb.x - mn.x) * (gm.x * rsqrtf(vr.x + BN_EPS)) + bt.x, 0.f);
    o.y = fmaxf((acc.y + cb.y - mn.y) * (gm.y * rsqrtf(vr.y + BN_EPS)) + bt.y, 0.f);
    o.z = fmaxf((acc.z + cb.z - mn.z) * (gm.z * rsqrtf(vr.z + BN_EPS)) + bt.z, 0.f);
    o.w = fmaxf((acc.w + cb.w - mn.w) * (gm.w * rsqrtf(vr.w + BN_EPS)) + bt.w, 0.f);
    float4 res = h4[v * 16 + gl];
    o.x += res.x; o.y += res.y; o.z += res.z; o.w += res.w;
    h4[v * 16 + gl] = o;
}

// ---------------- fused output MLP: out = x + relu(h@W1+b1)@W2 + b2 ----------------
__global__ void out_fused_kernel(const float* __restrict__ A,   // g_h (device ptr)
                                 const float* __restrict__ W1,
                                 const float* __restrict__ b1,
                                 const float* __restrict__ W2,
                                 const float* __restrict__ b2,
                                 const float* __restrict__ x,
                                 float* __restrict__ out) {
    __shared__ float hT[64 * 68];
    __shared__ float Ws[64 * 64];
    __shared__ float ts[64 * 68];
    __shared__ float W2s[HID * IN_DIM];
    __shared__ float b2s[IN_DIM];
    int tid = threadIdx.x;
    int n0 = blockIdx.x * 64;

    {
        const float4* W4 = (const float4*)W1;
        float4* Ws4 = (float4*)Ws;
        #pragma unroll
        for (int i = tid; i < 1024; i += 256) Ws4[i] = W4[i];
    }
    if (tid < HID * IN_DIM) W2s[tid] = W2[tid];
    if (tid < IN_DIM) b2s[tid] = b2[tid];
    {
        int nn = tid & 63;
        int kq4 = tid >> 6;
        int node = n0 + nn;
        const float4* A4 = (const float4*)A;
        #pragma unroll
        for (int q = 0; q < 4; q++) {
            int kq = kq4 * 4 + q;
            float4 hv = (node < N_NODES) ? A4[node * 16 + kq]
                                         : make_float4(0.f, 0.f, 0.f, 0.f);
            hT[(kq * 4 + 0) * 68 + nn] = hv.x;
            hT[(kq * 4 + 1) * 68 + nn] = hv.y;
            hT[(kq * 4 + 2) * 68 + nn] = hv.z;
            hT[(kq * 4 + 3) * 68 + nn] = hv.w;
        }
    }
    __syncthreads();

    int nq = tid & 15;
    int jq = tid >> 4;
    const float4* Ws4 = (const float4*)Ws;

    float4 acc0 = make_float4(0.f, 0.f, 0.f, 0.f);
    float4 acc1 = acc0, acc2 = acc0, acc3 = acc0;
    #pragma unroll
    for (int k = 0; k < 64; k++) {
        float4 wv = Ws4[k * 16 + jq];
        float4 hv = *(const float4*)&hT[k * 68 + nq * 4];
        acc0.x += hv.x * wv.x; acc0.y += hv.x * wv.y; acc0.z += hv.x * wv.z; acc0.w += hv.x * wv.w;
        acc1.x += hv.y * wv.x; acc1.y += hv.y * wv.y; acc1.z += hv.y * wv.z; acc1.w += hv.y * wv.w;
        acc2.x += hv.z * wv.x; acc2.y += hv.z * wv.y; acc2.z += hv.z * wv.z; acc2.w += hv.z * wv.w;
        acc3.x += hv.w * wv.x; acc3.y += hv.w * wv.y; acc3.z += hv.w * wv.z; acc3.w += hv.w * wv.w;
    }

    float4 bv = ((const float4*)b1)[jq];
    float4 accs[4] = {acc0, acc1, acc2, acc3};
    #pragma unroll
    for (int ni = 0; ni < 4; ni++) {
        int nloc = nq * 4 + ni;
        float4 r = accs[ni];
        r.x = fmaxf(r.x + bv.x, 0.f);
        r.y = fmaxf(r.y + bv.y, 0.f);
        r.z = fmaxf(r.z + bv.z, 0.f);
        r.w = fmaxf(r.w + bv.w, 0.f);
        *(float4*)&ts[nloc * 68 + jq * 4] = r;
    }
    __syncthreads();

    int nloc = tid >> 2;
    int m = tid & 3;
    int node = n0 + nloc;
    float acc = 0.f;
    #pragma unroll
    for (int l = 0; l < 64; l++) {
        acc += ts[nloc * 68 + l] * W2s[l * IN_DIM + m];
    }
    if (node < N_NODES) {
        out[node * IN_DIM + m] = x[node * IN_DIM + m] + b2s[m] + acc;
    }
}

// ---------------- launch ----------------
extern "C" void kernel_launch(void* const* d_in, const int* in_sizes, int n_in,
                              void* d_out, int out_size) {
    const float* x          = (const float*)d_in[0];
    const int*   edge_index = (const int*)d_in[1];
    const float* W_in       = (const float*)d_in[2];
    const float* b_in       = (const float*)d_in[3];
    const float* conv_w     = (const float*)d_in[4];   // [3,64,64]
    const float* conv_b     = (const float*)d_in[5];   // [3,64]
    const float* bn_gamma   = (const float*)d_in[6];
    const float* bn_beta    = (const float*)d_in[7];
    const float* bn_mean    = (const float*)d_in[8];
    const float* bn_var     = (const float*)d_in[9];
    const float* W1         = (const float*)d_in[10];
    const float* b1         = (const float*)d_in[11];
    const float* W2         = (const float*)d_in[12];
    const float* b2         = (const float*)d_in[13];
    float* out = (float*)d_out;

    void* p_h = nullptr;
    void* p_hwb = nullptr;
    cudaGetSymbolAddress(&p_h, g_h);
    cudaGetSymbolAddress(&p_hwb, g_hwb);
    float* d_h = (float*)p_h;
    uint2* d_hwb = (uint2*)p_hwb;

    const int TPB = 256;
    const int gridE = (N_EDGES + TPB - 1) / TPB;
    const int gridT = (N_NODES + 63) / 64;
    const int gridG = (N_NODES * 16 + TPB - 1) / TPB;   // 16-lane group per node

    // Launch order puts gemm1 at index 3 so the fixed ncu window profiles it.
    in_proj_kernel<<<gridT, TPB>>>(x, W_in, b_in);                        // 0
    count_deg_kernel<<<gridE, TPB>>>(edge_index);                         // 1
    scan_reduce_kernel<<<NBLK, SCAN_BLK>>>();                             // 2 (also dinv)
    gemm64_bf16_kernel<<<gridT, TPB>>>(d_h, conv_w + 0 * HID * HID, d_hwb); // 3  <- profiled
    scan_offsets_kernel<<<1, 256>>>();                                    // 4
    scan_write_kernel<<<NBLK, SCAN_BLK>>>();                              // 5
    fill_kernel<<<gridE, TPB>>>(edge_index);                              // 6 (also re-zeros deg)

    // layer 1 aggregate
    agg_kernel<<<gridG, TPB>>>(conv_b + 0 * HID,
                               bn_gamma + 0 * HID, bn_beta + 0 * HID,
                               bn_mean + 0 * HID, bn_var + 0 * HID);      // 7

    // layers 2..3
    for (int i = 1; i < 3; i++) {
        gemm64_bf16_kernel<<<gridT, TPB>>>(d_h, conv_w + i * HID * HID, d_hwb);
        agg_kernel<<<gridG, TPB>>>(conv_b + i * HID,
                                   bn_gamma + i * HID, bn_beta + i * HID,
                                   bn_mean + i * HID, bn_var + i * HID);
    }

    // fused output MLP + residual
    out_fused_kernel<<<gridT, TPB>>>(d_h, W1, b1, W2, b2, x, out);
}